// round 12
// baseline (speedup 1.0000x reference)
#include <cuda_runtime.h>

// ===================== compile-time CG machinery (host+device constexpr) =====================
__host__ __device__ constexpr double cfact(int n) { double r = 1.0; for (int i = 2; i <= n; i++) r *= (double)i; return r; }
__host__ __device__ constexpr double csqrt_(double x) { double g = x > 1.0 ? x : 1.0; for (int i = 0; i < 100; i++) g = 0.5 * (g + x / g); return g; }
__host__ __device__ constexpr double cg_d(int l1, int l2, int l, int m1, int m2) {
  const int m = m1 + m2;
  if (m < -l || m > l) return 0.0;
  double pre = csqrt_((2 * l + 1) * cfact(l + l1 - l2) * cfact(l - l1 + l2) * cfact(l1 + l2 - l) / cfact(l1 + l2 + l + 1));
  pre *= csqrt_(cfact(l + m) * cfact(l - m) * cfact(l1 - m1) * cfact(l1 + m1) * cfact(l2 - m2) * cfact(l2 + m2));
  double s = 0.0;
  for (int k = 0; k <= l1 + l2 - l; k++) {
    int e2 = l1 + l2 - l - k, e3 = l1 - m1 - k, e4 = l2 + m2 - k, e5 = l - l2 + m1 + k, e6 = l - l1 - m2 + k;
    if (e3 < 0 || e4 < 0 || e5 < 0 || e6 < 0) continue;
    double d = cfact(k) * cfact(e2) * cfact(e3) * cfact(e4) * cfact(e5) * cfact(e6);
    s += ((k & 1) ? -1.0 : 1.0) / d;
  }
  double v = pre * s;
  if (v < 1e-12 && v > -1e-12) return 0.0;
  return v;
}
__host__ __device__ constexpr int cmax_i(int a, int b) { return a > b ? a : b; }
__host__ __device__ constexpr int cmin_i(int a, int b) { return a < b ? a : b; }
__host__ __device__ constexpr int lmax_of(int a, int b) { return (a + b < 5) ? (a + b) : 5; }
__host__ __device__ constexpr int NTA_f(int l)     { return l == 0 ? 384 : l == 1 ? 640 : l == 2 ? 832 : l == 3 ? 896 : l == 4 ? 896 : 768; }
__host__ __device__ constexpr int STDOFF_f(int l)  { return l == 0 ? 0 : l == 1 ? 384 : l == 2 ? 1024 : l == 3 ? 1856 : l == 4 ? 2752 : 3648; }
__host__ __device__ constexpr int WOFF_f(int l)    { return l == 0 ? 0 : l == 1 ? 3072 : l == 2 ? 8192 : l == 3 ? 14848 : l == 4 ? 22016 : 29184; }
__host__ __device__ constexpr int ACTOFF_f(int l)  { return l == 0 ? 0 : l == 1 ? 8 : l == 2 ? 32 : l == 3 ? 72 : l == 4 ? 128 : 200; }
__host__ __device__ constexpr int chanoff_f(int L, int l1, int l2) {
  int off = 0;
  for (int a = 0; a <= 5; a++)
    for (int b = 0; b <= a; b++) {
      int lm = lmax_of(a, b);
      for (int l = a - b; l <= lm; l++)
        if (l == L) { if (a == l1 && b == l2) return off; off += 64; }
    }
  return 0;
}
__host__ __device__ constexpr int sumnl_f(int a, int b) { int s = 0; for (int l = a - b; l <= lmax_of(a, b); l++) s += 2 * l + 1; return s; }
__host__ __device__ constexpr int rowp_f(int a, int b) { return sumnl_f(a, b) | 1; }  // odd pad
__host__ __device__ constexpr int rowoff_f(int l1, int l2, int li) { return li * (2 * (l1 - l2) + li); }
// greedy chunking: each chunk <= 10 rows (keeps stage-A frag small)
__host__ __device__ constexpr int chunk_end_f(int l1, int l2, int lib) {
  int lmin = l1 - l2, nls = lmax_of(l1, l2) - lmin + 1;
  int rows = 0, lie = lib;
  for (int li = lib; li < nls; li++) {
    int L = lmin + li;
    if (rows + 2 * L + 1 > 10 && li > lib) break;
    rows += 2 * L + 1; lie = li;
  }
  return lie;
}
__host__ __device__ constexpr int nchunks_f(int l1, int l2) {
  int n = 0, lib = 0;
  int nls = lmax_of(l1, l2) - (l1 - l2) + 1;
  while (lib < nls) { lib = chunk_end_f(l1, l2, lib) + 1; n++; }
  return n;
}
__host__ __device__ constexpr int sched_f(int g) { return g < 8 ? g : 15 - g; }  // overflow -> light groups

template <int L1, int L2>
struct PairCG {
  static constexpr int LMIN = L1 - L2, LMAX = lmax_of(L1, L2), NLS = LMAX - LMIN + 1;
  static constexpr int NL1 = 2 * L1 + 1, NL2 = 2 * L2 + 1;
  float v[NLS][NL1][NL2];
  int stdidx[NLS];
  int widx[NLS];
  int ntl[NLS];
  __host__ __device__ constexpr PairCG() : v(), stdidx(), widx(), ntl() {
    for (int li = 0; li < NLS; li++) {
      const int L = LMIN + li;
      for (int a = 0; a < NL1; a++)
        for (int c = 0; c < NL2; c++)
          v[li][a][c] = (float)cg_d(L1, L2, L, a - L1, c - L2);
      stdidx[li] = STDOFF_f(L) + chanoff_f(L, L1, L2);
      widx[li]   = WOFF_f(L) + chanoff_f(L, L1, L2);
      ntl[li]    = NTA_f(L);
    }
  }
};

// ===================== device globals =====================
__device__ float d_invstd[4416];

__global__ void k_invstd(const float* __restrict__ s) {
  int i = blockIdx.x * blockDim.x + threadIdx.x;
  if (i < 4416) d_invstd[i] = 1.0f / (s[i] + 1e-5f);
}

#define BUFSTR 6400  // complex units per blk buffer (max round rowp sum = 100)

// ===================== stage A chunk: thread = channel, li in [LIB,LIE] =====================
template <int L1, int L2, int LIB, int LIE>
__device__ __forceinline__ void pairA_chunk(const float2* __restrict__ Fs, float2* __restrict__ blk, int ch) {
  constexpr PairCG<L1, L2> CG{};
  constexpr int NL1 = 2 * L1 + 1, NL2 = 2 * L2 + 1, LMIN = L1 - L2;
  constexpr int ROWP = rowp_f(L1, L2);
  constexpr int CB = rowoff_f(L1, L2, LIB);
  constexpr int CROWS = rowoff_f(L1, L2, LIE + 1) - CB;
  const int t = ch >> 3, s = ch & 7;
  const float2* Ap = Fs + ACTOFF_f(L1) + t * NL1;
  const float2* Bp = Fs + ACTOFF_f(L2) + s * NL2;
  float2 a[NL1];
#pragma unroll
  for (int i = 0; i < NL1; i++) a[i] = Ap[i];
  float2 frag[CROWS];
#pragma unroll
  for (int i = 0; i < CROWS; i++) { frag[i].x = 0.f; frag[i].y = 0.f; }
#pragma unroll
  for (int m2 = 0; m2 < NL2; m2++) {
    const float2 b = Bp[m2];
#pragma unroll
    for (int m1 = 0; m1 < NL1; m1++) {
      const float px = a[m1].x * b.x - a[m1].y * b.y;
      const float py = a[m1].x * b.y + a[m1].y * b.x;
#pragma unroll
      for (int li = LIB; li <= LIE; li++) {
        const int L = LMIN + li;
        const int midx = (m1 - L1) + (m2 - L2) + L;
        if (midx >= 0 && midx < 2 * L + 1) {
          const float c = CG.v[li][m1][m2];
          if (c != 0.f) {
            const int fi = rowoff_f(L1, L2, li) - CB + midx;
            frag[fi].x += c * px;
            frag[fi].y += c * py;
          }
        }
      }
    }
  }
#pragma unroll
  for (int li = LIB; li <= LIE; li++) {
    const int L = LMIN + li;
    const float istd = d_invstd[CG.stdidx[li] + ch];
#pragma unroll
    for (int m = 0; m < 2 * L + 1; m++) {
      const int row = rowoff_f(L1, L2, li) + m;
      const float2 f = frag[row - CB];
      blk[ch * ROWP + row] = make_float2(f.x * istd, f.y * istd);
    }
  }
}

// globally scheduled chunks: chunk with global index G runs on 64-thread group sched_f(G)
template <int L1, int L2, int LIB, int G>
__device__ __forceinline__ void pairA_sched(const float2* __restrict__ Fs, float2* __restrict__ blk, int ch, int hg) {
  constexpr int LIE = chunk_end_f(L1, L2, LIB);
  if (sched_f(G) == hg) pairA_chunk<L1, L2, LIB, LIE>(Fs, blk, ch);
  if constexpr (LIE < PairCG<L1, L2>::NLS - 1) pairA_sched<L1, L2, LIE + 1, G + 1>(Fs, blk, ch, hg);
}

// ===================== stage B: warp = (og, Q); owns o=2og,2og+1, rows 9Q..9Q+8 =============
template <int L1, int L2, int Q>
__device__ __forceinline__ void pairB_q(const float2* __restrict__ blk, const float2* __restrict__ wts,
                                        float2 (&acc0)[9], float2 (&acc1)[9], int og, int lane) {
  constexpr PairCG<L1, L2> CG{};
  constexpr int NLS = PairCG<L1, L2>::NLS, LMIN = L1 - L2;
  constexpr int ROWP = rowp_f(L1, L2);
#pragma unroll
  for (int li = 0; li < NLS; li++) {
    const int L = LMIN + li;
    const int LO = L * L, nl = 2 * L + 1;
    const int mlo = cmax_i(0, 9 * Q - LO);
    const int mhi = cmin_i(nl, 9 * Q + 9 - LO);
    if (mlo < mhi) {
      const int rowoff = rowoff_f(L1, L2, li);
      const float2* wp0 = wts + CG.widx[li] + (2 * og) * CG.ntl[li];
      const float2* wp1 = wp0 + CG.ntl[li];
#pragma unroll
      for (int h2 = 0; h2 < 2; h2++) {
        const int c = lane + 32 * h2;
        const float2 w0 = __ldg(wp0 + c);
        const float2 w1 = __ldg(wp1 + c);
        const float2* mp = blk + c * ROWP + rowoff;
#pragma unroll
        for (int m = mlo; m < mhi; m++) {
          const float2 mv = mp[m];
          const int i = LO + m - 9 * Q;
          acc0[i].x += w0.x * mv.x - w0.y * mv.y;
          acc0[i].y += w0.x * mv.y + w0.y * mv.x;
          acc1[i].x += w1.x * mv.x - w1.y * mv.y;
          acc1[i].y += w1.x * mv.y + w1.y * mv.x;
        }
      }
    }
  }
}

// ===================== round pieces =====================
template <int A0, int B0, int A1, int B1, int A2, int B2, int A3, int B3>
__device__ __forceinline__ void roundA(const float2* __restrict__ Fs, float2* __restrict__ blk, int tid) {
  const int hg = tid >> 6, ch = tid & 63;
  constexpr int T0 = 0;
  constexpr int T1 = T0 + 64 * rowp_f(A0, B0);
  constexpr int T2 = T1 + 64 * rowp_f(A1, B1);
  constexpr int T3 = T2 + 64 * rowp_f(A2, B2);
  constexpr int G0 = 0;
  constexpr int G1 = G0 + nchunks_f(A0, B0);
  constexpr int G2 = G1 + nchunks_f(A1, B1);
  constexpr int G3 = G2 + nchunks_f(A2, B2);
  pairA_sched<A0, B0, 0, G0>(Fs, blk + T0, ch, hg);
  pairA_sched<A1, B1, 0, G1>(Fs, blk + T1, ch, hg);
  pairA_sched<A2, B2, 0, G2>(Fs, blk + T2, ch, hg);
  pairA_sched<A3, B3, 0, G3>(Fs, blk + T3, ch, hg);
}

template <int A0, int B0, int A1, int B1, int A2, int B2, int A3, int B3, int Q>
__device__ __forceinline__ void roundB_q(const float2* __restrict__ blk, const float2* __restrict__ wts,
                                         float2 (&acc0)[9], float2 (&acc1)[9], int og, int lane) {
  constexpr int T0 = 0;
  constexpr int T1 = T0 + 64 * rowp_f(A0, B0);
  constexpr int T2 = T1 + 64 * rowp_f(A1, B1);
  constexpr int T3 = T2 + 64 * rowp_f(A2, B2);
  pairB_q<A0, B0, Q>(blk + T0, wts, acc0, acc1, og, lane);
  pairB_q<A1, B1, Q>(blk + T1, wts, acc0, acc1, og, lane);
  pairB_q<A2, B2, Q>(blk + T2, wts, acc0, acc1, og, lane);
  pairB_q<A3, B3, Q>(blk + T3, wts, acc0, acc1, og, lane);
}

template <int A0, int B0, int A1, int B1, int A2, int B2, int A3, int B3>
__device__ __forceinline__ void roundB(const float2* __restrict__ blk, const float2* __restrict__ wts,
                                       float2 (&acc0)[9], float2 (&acc1)[9], int og, int lane, int q) {
  if (q == 0)      roundB_q<A0, B0, A1, B1, A2, B2, A3, B3, 0>(blk, wts, acc0, acc1, og, lane);
  else if (q == 1) roundB_q<A0, B0, A1, B1, A2, B2, A3, B3, 1>(blk, wts, acc0, acc1, og, lane);
  else if (q == 2) roundB_q<A0, B0, A1, B1, A2, B2, A3, B3, 2>(blk, wts, acc0, acc1, og, lane);
  else             roundB_q<A0, B0, A1, B1, A2, B2, A3, B3, 3>(blk, wts, acc0, acc1, og, lane);
}

// ===================== fused kernel: pipelined rounds, double-buffered mid ==================
extern __shared__ float2 smem_[];

__global__ __launch_bounds__(512, 1) void k_fused(const float2* __restrict__ act,
                                                  const float2* __restrict__ wts,
                                                  float2* __restrict__ out) {
  const int b = blockIdx.x, tid = threadIdx.x;
  const int warp = tid >> 5, lane = tid & 31;
  const int og = warp & 3, q = warp >> 2;   // warp owns o=2og..2og+1, rows 9q..9q+8
  float2* Fs = smem_;                        // 288 complex activations
  float2* buf0 = smem_ + 288;                // mid buffer A
  float2* buf1 = buf0 + BUFSTR;              // mid buffer B

  for (int i = tid; i < 288; i += 512) Fs[i] = act[b * 288 + i];
  float2 acc0[9], acc1[9];
#pragma unroll
  for (int i = 0; i < 9; i++) {
    acc0[i].x = 0.f; acc0[i].y = 0.f;
    acc1[i].x = 0.f; acc1[i].y = 0.f;
  }
  __syncthreads();

  // pipeline: A(r+1) overlaps B(r); heavy-first pair order inside each round
  roundA<5, 4, 3, 3, 2, 1, 5, 0>(Fs, buf0, tid);
  __syncthreads();
  roundA<4, 3, 4, 4, 5, 1, 3, 0>(Fs, buf1, tid);
  roundB<5, 4, 3, 3, 2, 1, 5, 0>(buf0, wts, acc0, acc1, og, lane, q);
  __syncthreads();
  roundA<5, 5, 5, 3, 2, 2, 2, 0>(Fs, buf0, tid);
  roundB<4, 3, 4, 4, 5, 1, 3, 0>(buf1, wts, acc0, acc1, og, lane, q);
  __syncthreads();
  roundA<4, 2, 3, 2, 3, 1, 1, 1>(Fs, buf1, tid);
  roundB<5, 5, 5, 3, 2, 2, 2, 0>(buf0, wts, acc0, acc1, og, lane, q);
  __syncthreads();
  roundA<5, 2, 4, 1, 4, 0, 1, 0>(Fs, buf0, tid);
  roundB<4, 2, 3, 2, 3, 1, 1, 1>(buf1, wts, acc0, acc1, og, lane, q);
  __syncthreads();
  {  // A of final pair (0,0) into buf1 (its single chunk -> group 0), overlapped with B(r4)
    const int hg = tid >> 6, ch = tid & 63;
    pairA_sched<0, 0, 0, 0>(Fs, buf1, ch, hg);
  }
  roundB<5, 2, 4, 1, 4, 0, 1, 0>(buf0, wts, acc0, acc1, og, lane, q);
  __syncthreads();
  if (q == 0) pairB_q<0, 0, 0>(buf1, wts, acc0, acc1, og, lane);

  // epilogue: shfl-reduce lane partials; lane 0 stores both o values of each row
#pragma unroll
  for (int i = 0; i < 9; i++) {
    float2 v0 = acc0[i], v1 = acc1[i];
#pragma unroll
    for (int off = 16; off; off >>= 1) {
      v0.x += __shfl_xor_sync(0xffffffffu, v0.x, off);
      v0.y += __shfl_xor_sync(0xffffffffu, v0.y, off);
      v1.x += __shfl_xor_sync(0xffffffffu, v1.x, off);
      v1.y += __shfl_xor_sync(0xffffffffu, v1.y, off);
    }
    if (lane == 0) {
      const int r = 9 * q + i;
      const int l = (r >= 25) ? 5 : (r >= 16) ? 4 : (r >= 9) ? 3 : (r >= 4) ? 2 : (r >= 1) ? 1 : 0;
      const int m = r - l * l;
      const int nl = 2 * l + 1;
      out[b * 288 + ACTOFF_f(l) + (2 * og) * nl + m] = v0;
      out[b * 288 + ACTOFF_f(l) + (2 * og + 1) * nl + m] = v1;
    }
  }
}

// ===================== launch =====================
extern "C" void kernel_launch(void* const* d_in, const int* in_sizes, int n_in,
                              void* d_out, int out_size) {
  const float2* act = nullptr;
  const float2* wts = nullptr;
  const float* mstd = nullptr;
  int B = 1024;
  for (int i = 0; i < n_in; i++) {
    if (in_sizes[i] == 4416) mstd = (const float*)d_in[i];
    else if (in_sizes[i] == 70656) wts = (const float2*)d_in[i];
    else { act = (const float2*)d_in[i]; B = in_sizes[i] / 576; }
  }
  float2* out = (float2*)d_out;

  k_invstd<<<(4416 + 255) / 256, 256>>>(mstd);

  const int smem = (288 + 2 * BUFSTR) * (int)sizeof(float2);  // ~104.7 KB
  cudaFuncSetAttribute(k_fused, cudaFuncAttributeMaxDynamicSharedMemorySize, smem);
  k_fused<<<B, 512, smem>>>(act, wts, out);
}

// round 13
// speedup vs baseline: 1.1293x; 1.1293x over previous
#include <cuda_runtime.h>

// ===================== compile-time CG machinery (host+device constexpr) =====================
__host__ __device__ constexpr double cfact(int n) { double r = 1.0; for (int i = 2; i <= n; i++) r *= (double)i; return r; }
__host__ __device__ constexpr double csqrt_(double x) { double g = x > 1.0 ? x : 1.0; for (int i = 0; i < 100; i++) g = 0.5 * (g + x / g); return g; }
__host__ __device__ constexpr double cg_d(int l1, int l2, int l, int m1, int m2) {
  const int m = m1 + m2;
  if (m < -l || m > l) return 0.0;
  double pre = csqrt_((2 * l + 1) * cfact(l + l1 - l2) * cfact(l - l1 + l2) * cfact(l1 + l2 - l) / cfact(l1 + l2 + l + 1));
  pre *= csqrt_(cfact(l + m) * cfact(l - m) * cfact(l1 - m1) * cfact(l1 + m1) * cfact(l2 - m2) * cfact(l2 + m2));
  double s = 0.0;
  for (int k = 0; k <= l1 + l2 - l; k++) {
    int e2 = l1 + l2 - l - k, e3 = l1 - m1 - k, e4 = l2 + m2 - k, e5 = l - l2 + m1 + k, e6 = l - l1 - m2 + k;
    if (e3 < 0 || e4 < 0 || e5 < 0 || e6 < 0) continue;
    double d = cfact(k) * cfact(e2) * cfact(e3) * cfact(e4) * cfact(e5) * cfact(e6);
    s += ((k & 1) ? -1.0 : 1.0) / d;
  }
  double v = pre * s;
  if (v < 1e-12 && v > -1e-12) return 0.0;
  return v;
}
__host__ __device__ constexpr int cmax_i(int a, int b) { return a > b ? a : b; }
__host__ __device__ constexpr int cmin_i(int a, int b) { return a < b ? a : b; }
__host__ __device__ constexpr int lmax_of(int a, int b) { return (a + b < 5) ? (a + b) : 5; }
__host__ __device__ constexpr int NTA_f(int l)     { return l == 0 ? 384 : l == 1 ? 640 : l == 2 ? 832 : l == 3 ? 896 : l == 4 ? 896 : 768; }
__host__ __device__ constexpr int STDOFF_f(int l)  { return l == 0 ? 0 : l == 1 ? 384 : l == 2 ? 1024 : l == 3 ? 1856 : l == 4 ? 2752 : 3648; }
__host__ __device__ constexpr int WOFF_f(int l)    { return l == 0 ? 0 : l == 1 ? 3072 : l == 2 ? 8192 : l == 3 ? 14848 : l == 4 ? 22016 : 29184; }
__host__ __device__ constexpr int ACTOFF_f(int l)  { return l == 0 ? 0 : l == 1 ? 8 : l == 2 ? 32 : l == 3 ? 72 : l == 4 ? 128 : 200; }
__host__ __device__ constexpr int chanoff_f(int L, int l1, int l2) {
  int off = 0;
  for (int a = 0; a <= 5; a++)
    for (int b = 0; b <= a; b++) {
      int lm = lmax_of(a, b);
      for (int l = a - b; l <= lm; l++)
        if (l == L) { if (a == l1 && b == l2) return off; off += 64; }
    }
  return 0;
}
__host__ __device__ constexpr int sumnl_f(int a, int b) { int s = 0; for (int l = a - b; l <= lmax_of(a, b); l++) s += 2 * l + 1; return s; }
__host__ __device__ constexpr int rowp_f(int a, int b) { return sumnl_f(a, b) | 1; }  // odd pad
__host__ __device__ constexpr int rowoff_f(int l1, int l2, int li) { return li * (2 * (l1 - l2) + li); }
// greedy chunking: each chunk <= 10 rows (keeps stage-A frag small)
__host__ __device__ constexpr int chunk_end_f(int l1, int l2, int lib) {
  int lmin = l1 - l2, nls = lmax_of(l1, l2) - lmin + 1;
  int rows = 0, lie = lib;
  for (int li = lib; li < nls; li++) {
    int L = lmin + li;
    if (rows + 2 * L + 1 > 10 && li > lib) break;
    rows += 2 * L + 1; lie = li;
  }
  return lie;
}

template <int L1, int L2>
struct PairCG {
  static constexpr int LMIN = L1 - L2, LMAX = lmax_of(L1, L2), NLS = LMAX - LMIN + 1;
  static constexpr int NL1 = 2 * L1 + 1, NL2 = 2 * L2 + 1;
  float v[NLS][NL1][NL2];
  int stdidx[NLS];
  int widx[NLS];
  int ntl[NLS];
  __host__ __device__ constexpr PairCG() : v(), stdidx(), widx(), ntl() {
    for (int li = 0; li < NLS; li++) {
      const int L = LMIN + li;
      for (int a = 0; a < NL1; a++)
        for (int c = 0; c < NL2; c++)
          v[li][a][c] = (float)cg_d(L1, L2, L, a - L1, c - L2);
      stdidx[li] = STDOFF_f(L) + chanoff_f(L, L1, L2);
      widx[li]   = WOFF_f(L) + chanoff_f(L, L1, L2);
      ntl[li]    = NTA_f(L);
    }
  }
};

// ===================== device globals =====================
__device__ float d_invstd[4416];

__global__ void k_invstd(const float* __restrict__ s) {
  int i = blockIdx.x * blockDim.x + threadIdx.x;
  if (i < 4416) d_invstd[i] = 1.0f / (s[i] + 1e-5f);
}

#define BUFSTR 6400  // complex units per blk buffer (max round rowp sum = 100)

// ===================== stage A chunk: thread = channel, li in [LIB,LIE] =====================
template <int L1, int L2, int LIB, int LIE>
__device__ __forceinline__ void pairA_chunk(const float2* __restrict__ Fs, float2* __restrict__ blk, int ch) {
  constexpr PairCG<L1, L2> CG{};
  constexpr int NL1 = 2 * L1 + 1, NL2 = 2 * L2 + 1, LMIN = L1 - L2;
  constexpr int ROWP = rowp_f(L1, L2);
  constexpr int CB = rowoff_f(L1, L2, LIB);
  constexpr int CROWS = rowoff_f(L1, L2, LIE + 1) - CB;
  const int t = ch >> 3, s = ch & 7;
  const float2* Ap = Fs + ACTOFF_f(L1) + t * NL1;
  const float2* Bp = Fs + ACTOFF_f(L2) + s * NL2;
  float2 a[NL1];
#pragma unroll
  for (int i = 0; i < NL1; i++) a[i] = Ap[i];
  float2 frag[CROWS];
#pragma unroll
  for (int i = 0; i < CROWS; i++) { frag[i].x = 0.f; frag[i].y = 0.f; }
#pragma unroll
  for (int m2 = 0; m2 < NL2; m2++) {
    const float2 b = Bp[m2];
#pragma unroll
    for (int m1 = 0; m1 < NL1; m1++) {
      const float px = a[m1].x * b.x - a[m1].y * b.y;
      const float py = a[m1].x * b.y + a[m1].y * b.x;
#pragma unroll
      for (int li = LIB; li <= LIE; li++) {
        const int L = LMIN + li;
        const int midx = (m1 - L1) + (m2 - L2) + L;
        if (midx >= 0 && midx < 2 * L + 1) {
          const float c = CG.v[li][m1][m2];
          if (c != 0.f) {
            const int fi = rowoff_f(L1, L2, li) - CB + midx;
            frag[fi].x += c * px;
            frag[fi].y += c * py;
          }
        }
      }
    }
  }
#pragma unroll
  for (int li = LIB; li <= LIE; li++) {
    const int L = LMIN + li;
    const float istd = d_invstd[CG.stdidx[li] + ch];
#pragma unroll
    for (int m = 0; m < 2 * L + 1; m++) {
      const int row = rowoff_f(L1, L2, li) + m;
      const float2 f = frag[row - CB];
      blk[ch * ROWP + row] = make_float2(f.x * istd, f.y * istd);
    }
  }
}

// chunks assigned round-robin to the two 64-thread halves (ah = 0/1) of a pair's thread group
template <int L1, int L2, int LIB, int IDX>
__device__ __forceinline__ void pairA_rec(const float2* __restrict__ Fs, float2* __restrict__ blk, int ch, int ah) {
  constexpr int LIE = chunk_end_f(L1, L2, LIB);
  if ((IDX & 1) == ah) pairA_chunk<L1, L2, LIB, LIE>(Fs, blk, ch);
  if constexpr (LIE < PairCG<L1, L2>::NLS - 1) pairA_rec<L1, L2, LIE + 1, IDX + 1>(Fs, blk, ch, ah);
}

// ===================== stage B: warp = (og, Q); owns o=2og,2og+1, rows 9Q..9Q+8 =============
template <int L1, int L2, int Q>
__device__ __forceinline__ void pairB_q(const float2* __restrict__ blk, const float2* __restrict__ wts,
                                        float2 (&acc0)[9], float2 (&acc1)[9], int og, int lane) {
  constexpr PairCG<L1, L2> CG{};
  constexpr int NLS = PairCG<L1, L2>::NLS, LMIN = L1 - L2;
  constexpr int ROWP = rowp_f(L1, L2);
#pragma unroll
  for (int li = 0; li < NLS; li++) {
    const int L = LMIN + li;
    const int LO = L * L, nl = 2 * L + 1;
    const int mlo = cmax_i(0, 9 * Q - LO);
    const int mhi = cmin_i(nl, 9 * Q + 9 - LO);
    if (mlo < mhi) {
      const int rowoff = rowoff_f(L1, L2, li);
      const float2* wp0 = wts + CG.widx[li] + (2 * og) * CG.ntl[li];
      const float2* wp1 = wp0 + CG.ntl[li];
#pragma unroll
      for (int h2 = 0; h2 < 2; h2++) {
        const int c = lane + 32 * h2;
        const float2 w0 = __ldg(wp0 + c);
        const float2 w1 = __ldg(wp1 + c);
        const float2* mp = blk + c * ROWP + rowoff;
#pragma unroll
        for (int m = mlo; m < mhi; m++) {
          const float2 mv = mp[m];
          const int i = LO + m - 9 * Q;
          acc0[i].x += w0.x * mv.x - w0.y * mv.y;
          acc0[i].y += w0.x * mv.y + w0.y * mv.x;
          acc1[i].x += w1.x * mv.x - w1.y * mv.y;
          acc1[i].y += w1.x * mv.y + w1.y * mv.x;
        }
      }
    }
  }
}

// ===================== round pieces (stage A identical to R11) ==============================
template <int A0, int B0, int A1, int B1, int A2, int B2, int A3, int B3>
__device__ __forceinline__ void roundA(const float2* __restrict__ Fs, float2* __restrict__ blk, int tid) {
  const int p = tid >> 7, t = tid & 127, ch = t & 63, ah = t >> 6;
  constexpr int T0 = 0;
  constexpr int T1 = T0 + 64 * rowp_f(A0, B0);
  constexpr int T2 = T1 + 64 * rowp_f(A1, B1);
  constexpr int T3 = T2 + 64 * rowp_f(A2, B2);
  if (p == 0)      pairA_rec<A0, B0, 0, 0>(Fs, blk + T0, ch, ah);
  else if (p == 1) pairA_rec<A1, B1, 0, 0>(Fs, blk + T1, ch, ah);
  else if (p == 2) pairA_rec<A2, B2, 0, 0>(Fs, blk + T2, ch, ah);
  else             pairA_rec<A3, B3, 0, 0>(Fs, blk + T3, ch, ah);
}

template <int A0, int B0, int A1, int B1, int A2, int B2, int A3, int B3, int Q>
__device__ __forceinline__ void roundB_q(const float2* __restrict__ blk, const float2* __restrict__ wts,
                                         float2 (&acc0)[9], float2 (&acc1)[9], int og, int lane) {
  constexpr int T0 = 0;
  constexpr int T1 = T0 + 64 * rowp_f(A0, B0);
  constexpr int T2 = T1 + 64 * rowp_f(A1, B1);
  constexpr int T3 = T2 + 64 * rowp_f(A2, B2);
  pairB_q<A0, B0, Q>(blk + T0, wts, acc0, acc1, og, lane);
  pairB_q<A1, B1, Q>(blk + T1, wts, acc0, acc1, og, lane);
  pairB_q<A2, B2, Q>(blk + T2, wts, acc0, acc1, og, lane);
  pairB_q<A3, B3, Q>(blk + T3, wts, acc0, acc1, og, lane);
}

template <int A0, int B0, int A1, int B1, int A2, int B2, int A3, int B3>
__device__ __forceinline__ void roundB(const float2* __restrict__ blk, const float2* __restrict__ wts,
                                       float2 (&acc0)[9], float2 (&acc1)[9], int og, int lane, int q) {
  if (q == 0)      roundB_q<A0, B0, A1, B1, A2, B2, A3, B3, 0>(blk, wts, acc0, acc1, og, lane);
  else if (q == 1) roundB_q<A0, B0, A1, B1, A2, B2, A3, B3, 1>(blk, wts, acc0, acc1, og, lane);
  else if (q == 2) roundB_q<A0, B0, A1, B1, A2, B2, A3, B3, 2>(blk, wts, acc0, acc1, og, lane);
  else             roundB_q<A0, B0, A1, B1, A2, B2, A3, B3, 3>(blk, wts, acc0, acc1, og, lane);
}

// ===================== fused kernel: pipelined rounds, double-buffered mid ==================
extern __shared__ float2 smem_[];

__global__ __launch_bounds__(512, 1) void k_fused(const float2* __restrict__ act,
                                                  const float2* __restrict__ wts,
                                                  float2* __restrict__ out) {
  const int b = blockIdx.x, tid = threadIdx.x;
  const int warp = tid >> 5, lane = tid & 31;
  const int og = warp & 3, q = warp >> 2;   // warp owns o=2og..2og+1, rows 9q..9q+8
  float2* Fs = smem_;                        // 288 complex activations
  float2* buf0 = smem_ + 288;                // mid buffer A
  float2* buf1 = buf0 + BUFSTR;              // mid buffer B

  for (int i = tid; i < 288; i += 512) Fs[i] = act[b * 288 + i];
  float2 acc0[9], acc1[9];
#pragma unroll
  for (int i = 0; i < 9; i++) {
    acc0[i].x = 0.f; acc0[i].y = 0.f;
    acc1[i].x = 0.f; acc1[i].y = 0.f;
  }
  __syncthreads();

  // pipeline: A(r+1) overlaps B(r); one barrier per stage boundary (R11 structure)
  roundA<3, 3, 5, 4, 2, 1, 5, 0>(Fs, buf0, tid);
  __syncthreads();
  roundA<4, 4, 4, 3, 5, 1, 3, 0>(Fs, buf1, tid);
  roundB<3, 3, 5, 4, 2, 1, 5, 0>(buf0, wts, acc0, acc1, og, lane, q);
  __syncthreads();
  roundA<5, 5, 5, 3, 2, 2, 2, 0>(Fs, buf0, tid);
  roundB<4, 4, 4, 3, 5, 1, 3, 0>(buf1, wts, acc0, acc1, og, lane, q);
  __syncthreads();
  roundA<3, 2, 4, 2, 3, 1, 1, 1>(Fs, buf1, tid);
  roundB<5, 5, 5, 3, 2, 2, 2, 0>(buf0, wts, acc0, acc1, og, lane, q);
  __syncthreads();
  roundA<4, 1, 5, 2, 4, 0, 1, 0>(Fs, buf0, tid);
  roundB<3, 2, 4, 2, 3, 1, 1, 1>(buf1, wts, acc0, acc1, og, lane, q);
  __syncthreads();
  {  // A of final pair (0,0) into buf1 (group 0 only), overlapped with B(r4)
    const int p = tid >> 7, t = tid & 127, ch = t & 63, ah = t >> 6;
    if (p == 0) pairA_rec<0, 0, 0, 0>(Fs, buf1, ch, ah);
  }
  roundB<4, 1, 5, 2, 4, 0, 1, 0>(buf0, wts, acc0, acc1, og, lane, q);
  __syncthreads();
  if (q == 0) pairB_q<0, 0, 0>(buf1, wts, acc0, acc1, og, lane);

  // epilogue: shfl-reduce lane partials; lane 0 stores both o values of each row
#pragma unroll
  for (int i = 0; i < 9; i++) {
    float2 v0 = acc0[i], v1 = acc1[i];
#pragma unroll
    for (int off = 16; off; off >>= 1) {
      v0.x += __shfl_xor_sync(0xffffffffu, v0.x, off);
      v0.y += __shfl_xor_sync(0xffffffffu, v0.y, off);
      v1.x += __shfl_xor_sync(0xffffffffu, v1.x, off);
      v1.y += __shfl_xor_sync(0xffffffffu, v1.y, off);
    }
    if (lane == 0) {
      const int r = 9 * q + i;
      const int l = (r >= 25) ? 5 : (r >= 16) ? 4 : (r >= 9) ? 3 : (r >= 4) ? 2 : (r >= 1) ? 1 : 0;
      const int m = r - l * l;
      const int nl = 2 * l + 1;
      out[b * 288 + ACTOFF_f(l) + (2 * og) * nl + m] = v0;
      out[b * 288 + ACTOFF_f(l) + (2 * og + 1) * nl + m] = v1;
    }
  }
}

// ===================== launch =====================
extern "C" void kernel_launch(void* const* d_in, const int* in_sizes, int n_in,
                              void* d_out, int out_size) {
  const float2* act = nullptr;
  const float2* wts = nullptr;
  const float* mstd = nullptr;
  int B = 1024;
  for (int i = 0; i < n_in; i++) {
    if (in_sizes[i] == 4416) mstd = (const float*)d_in[i];
    else if (in_sizes[i] == 70656) wts = (const float2*)d_in[i];
    else { act = (const float2*)d_in[i]; B = in_sizes[i] / 576; }
  }
  float2* out = (float2*)d_out;

  k_invstd<<<(4416 + 255) / 256, 256>>>(mstd);

  const int smem = (288 + 2 * BUFSTR) * (int)sizeof(float2);  // ~104.7 KB
  cudaFuncSetAttribute(k_fused, cudaFuncAttributeMaxDynamicSharedMemorySize, smem);
  k_fused<<<B, 512, smem>>>(act, wts, out);
}

// round 14
// speedup vs baseline: 1.3070x; 1.1573x over previous
#include <cuda_runtime.h>

// ===================== compile-time CG machinery (host+device constexpr) =====================
__host__ __device__ constexpr double cfact(int n) { double r = 1.0; for (int i = 2; i <= n; i++) r *= (double)i; return r; }
__host__ __device__ constexpr double csqrt_(double x) { double g = x > 1.0 ? x : 1.0; for (int i = 0; i < 100; i++) g = 0.5 * (g + x / g); return g; }
__host__ __device__ constexpr double cg_d(int l1, int l2, int l, int m1, int m2) {
  const int m = m1 + m2;
  if (m < -l || m > l) return 0.0;
  double pre = csqrt_((2 * l + 1) * cfact(l + l1 - l2) * cfact(l - l1 + l2) * cfact(l1 + l2 - l) / cfact(l1 + l2 + l + 1));
  pre *= csqrt_(cfact(l + m) * cfact(l - m) * cfact(l1 - m1) * cfact(l1 + m1) * cfact(l2 - m2) * cfact(l2 + m2));
  double s = 0.0;
  for (int k = 0; k <= l1 + l2 - l; k++) {
    int e2 = l1 + l2 - l - k, e3 = l1 - m1 - k, e4 = l2 + m2 - k, e5 = l - l2 + m1 + k, e6 = l - l1 - m2 + k;
    if (e3 < 0 || e4 < 0 || e5 < 0 || e6 < 0) continue;
    double d = cfact(k) * cfact(e2) * cfact(e3) * cfact(e4) * cfact(e5) * cfact(e6);
    s += ((k & 1) ? -1.0 : 1.0) / d;
  }
  double v = pre * s;
  if (v < 1e-12 && v > -1e-12) return 0.0;
  return v;
}
__host__ __device__ constexpr int lmax_of(int a, int b) { return (a + b < 5) ? (a + b) : 5; }
__host__ __device__ constexpr int NTA_f(int l)     { return l == 0 ? 384 : l == 1 ? 640 : l == 2 ? 832 : l == 3 ? 896 : l == 4 ? 896 : 768; }
__host__ __device__ constexpr int STDOFF_f(int l)  { return l == 0 ? 0 : l == 1 ? 384 : l == 2 ? 1024 : l == 3 ? 1856 : l == 4 ? 2752 : 3648; }
__host__ __device__ constexpr int WOFF_f(int l)    { return l == 0 ? 0 : l == 1 ? 3072 : l == 2 ? 8192 : l == 3 ? 14848 : l == 4 ? 22016 : 29184; }
__host__ __device__ constexpr int ACTOFF_f(int l)  { return l == 0 ? 0 : l == 1 ? 8 : l == 2 ? 32 : l == 3 ? 72 : l == 4 ? 128 : 200; }
__host__ __device__ constexpr int chanoff_f(int L, int l1, int l2) {
  int off = 0;
  for (int a = 0; a <= 5; a++)
    for (int b = 0; b <= a; b++) {
      int lm = lmax_of(a, b);
      for (int l = a - b; l <= lm; l++)
        if (l == L) { if (a == l1 && b == l2) return off; off += 64; }
    }
  return 0;
}
__host__ __device__ constexpr int sumnl_f(int a, int b) { int s = 0; for (int l = a - b; l <= lmax_of(a, b); l++) s += 2 * l + 1; return s; }
__host__ __device__ constexpr int rowp_f(int a, int b) { return sumnl_f(a, b) | 1; }  // odd pad
__host__ __device__ constexpr int rowoff_f(int l1, int l2, int li) { return li * (2 * (l1 - l2) + li); }
// greedy chunking: each chunk <= 18 rows (producer warps have no acc coexistence)
__host__ __device__ constexpr int chunk_end_f(int l1, int l2, int lib) {
  int lmin = l1 - l2, nls = lmax_of(l1, l2) - lmin + 1;
  int rows = 0, lie = lib;
  for (int li = lib; li < nls; li++) {
    int L = lmin + li;
    if (rows + 2 * L + 1 > 18 && li > lib) break;
    rows += 2 * L + 1; lie = li;
  }
  return lie;
}

template <int L1, int L2>
struct PairCG {
  static constexpr int LMIN = L1 - L2, LMAX = lmax_of(L1, L2), NLS = LMAX - LMIN + 1;
  static constexpr int NL1 = 2 * L1 + 1, NL2 = 2 * L2 + 1;
  float v[NLS][NL1][NL2];
  int stdidx[NLS];
  int widx[NLS];
  int ntl[NLS];
  __host__ __device__ constexpr PairCG() : v(), stdidx(), widx(), ntl() {
    for (int li = 0; li < NLS; li++) {
      const int L = LMIN + li;
      for (int a = 0; a < NL1; a++)
        for (int c = 0; c < NL2; c++)
          v[li][a][c] = (float)cg_d(L1, L2, L, a - L1, c - L2);
      stdidx[li] = STDOFF_f(L) + chanoff_f(L, L1, L2);
      widx[li]   = WOFF_f(L) + chanoff_f(L, L1, L2);
      ntl[li]    = NTA_f(L);
    }
  }
};

// ===================== device globals =====================
__device__ float d_invstd[4416];

__global__ void k_invstd(const float* __restrict__ s) {
  int i = blockIdx.x * blockDim.x + threadIdx.x;
  if (i < 4416) d_invstd[i] = 1.0f / (s[i] + 1e-5f);
}

#define BUFSTR 6400  // complex units per blk buffer (max round rowp sum = 100)

// ===================== producer: one chunk of a pair, thread = channel ======================
template <int L1, int L2, int LIB, int LIE>
__device__ __forceinline__ void pairA_chunk(const float2* __restrict__ Fs, float2* __restrict__ blk, int ch) {
  constexpr PairCG<L1, L2> CG{};
  constexpr int NL1 = 2 * L1 + 1, NL2 = 2 * L2 + 1, LMIN = L1 - L2;
  constexpr int ROWP = rowp_f(L1, L2);
  constexpr int CB = rowoff_f(L1, L2, LIB);
  constexpr int CROWS = rowoff_f(L1, L2, LIE + 1) - CB;
  const int t = ch >> 3, s = ch & 7;
  const float2* Ap = Fs + ACTOFF_f(L1) + t * NL1;
  const float2* Bp = Fs + ACTOFF_f(L2) + s * NL2;
  float2 a[NL1];
#pragma unroll
  for (int i = 0; i < NL1; i++) a[i] = Ap[i];
  float2 frag[CROWS];
#pragma unroll
  for (int i = 0; i < CROWS; i++) { frag[i].x = 0.f; frag[i].y = 0.f; }
#pragma unroll
  for (int m2 = 0; m2 < NL2; m2++) {
    const float2 b = Bp[m2];
#pragma unroll
    for (int m1 = 0; m1 < NL1; m1++) {
      const float px = a[m1].x * b.x - a[m1].y * b.y;
      const float py = a[m1].x * b.y + a[m1].y * b.x;
#pragma unroll
      for (int li = LIB; li <= LIE; li++) {
        const int L = LMIN + li;
        const int midx = (m1 - L1) + (m2 - L2) + L;
        if (midx >= 0 && midx < 2 * L + 1) {
          const float c = CG.v[li][m1][m2];
          if (c != 0.f) {
            const int fi = rowoff_f(L1, L2, li) - CB + midx;
            frag[fi].x += c * px;
            frag[fi].y += c * py;
          }
        }
      }
    }
  }
#pragma unroll
  for (int li = LIB; li <= LIE; li++) {
    const int L = LMIN + li;
    const float istd = d_invstd[CG.stdidx[li] + ch];
#pragma unroll
    for (int m = 0; m < 2 * L + 1; m++) {
      const int row = rowoff_f(L1, L2, li) + m;
      const float2 f = frag[row - CB];
      blk[ch * ROWP + row] = make_float2(f.x * istd, f.y * istd);
    }
  }
}

// producer runs ALL chunks of its pair
template <int L1, int L2, int LIB>
__device__ __forceinline__ void pairA_all(const float2* __restrict__ Fs, float2* __restrict__ blk, int ch) {
  constexpr int LIE = chunk_end_f(L1, L2, LIB);
  pairA_chunk<L1, L2, LIB, LIE>(Fs, blk, ch);
  if constexpr (LIE < PairCG<L1, L2>::NLS - 1) pairA_all<L1, L2, LIE + 1>(Fs, blk, ch);
}

// ===================== consumer: warp = o, full 36-row acc ==================================
template <int L1, int L2>
__device__ __forceinline__ void pairB_o(const float2* __restrict__ blk, const float2* __restrict__ wts,
                                        float2 (&acc)[36], int o, int lane) {
  constexpr PairCG<L1, L2> CG{};
  constexpr int NLS = PairCG<L1, L2>::NLS, LMIN = L1 - L2;
  constexpr int ROWP = rowp_f(L1, L2);
#pragma unroll
  for (int li = 0; li < NLS; li++) {
    const int L = LMIN + li;
    const int LO = L * L, nl = 2 * L + 1;
    const int rowoff = rowoff_f(L1, L2, li);
    const float2* wp = wts + CG.widx[li] + o * CG.ntl[li];
#pragma unroll
    for (int h2 = 0; h2 < 2; h2++) {
      const int c = lane + 32 * h2;
      const float2 w = __ldg(wp + c);
      const float2* mp = blk + c * ROWP + rowoff;
#pragma unroll
      for (int m = 0; m < nl; m++) {
        const float2 mv = mp[m];
        acc[LO + m].x += w.x * mv.x - w.y * mv.y;
        acc[LO + m].y += w.x * mv.y + w.y * mv.x;
      }
    }
  }
}

// ===================== round pieces =====================
template <int A0, int B0, int A1, int B1, int A2, int B2, int A3, int B3>
__device__ __forceinline__ void roundA(const float2* __restrict__ Fs, float2* __restrict__ blk, int wid, int lane) {
  const int p = wid >> 1, ch = ((wid & 1) << 5) | lane;
  constexpr int T0 = 0;
  constexpr int T1 = T0 + 64 * rowp_f(A0, B0);
  constexpr int T2 = T1 + 64 * rowp_f(A1, B1);
  constexpr int T3 = T2 + 64 * rowp_f(A2, B2);
  if (p == 0)      pairA_all<A0, B0, 0>(Fs, blk + T0, ch);
  else if (p == 1) pairA_all<A1, B1, 0>(Fs, blk + T1, ch);
  else if (p == 2) pairA_all<A2, B2, 0>(Fs, blk + T2, ch);
  else             pairA_all<A3, B3, 0>(Fs, blk + T3, ch);
}

template <int A0, int B0, int A1, int B1, int A2, int B2, int A3, int B3>
__device__ __forceinline__ void roundB(const float2* __restrict__ blk, const float2* __restrict__ wts,
                                       float2 (&acc)[36], int o, int lane) {
  constexpr int T0 = 0;
  constexpr int T1 = T0 + 64 * rowp_f(A0, B0);
  constexpr int T2 = T1 + 64 * rowp_f(A1, B1);
  constexpr int T3 = T2 + 64 * rowp_f(A2, B2);
  pairB_o<A0, B0>(blk + T0, wts, acc, o, lane);
  pairB_o<A1, B1>(blk + T1, wts, acc, o, lane);
  pairB_o<A2, B2>(blk + T2, wts, acc, o, lane);
  pairB_o<A3, B3>(blk + T3, wts, acc, o, lane);
}

// ===================== fused kernel: warp-specialized producer/consumer pipeline ============
extern __shared__ float2 smem_[];

__global__ __launch_bounds__(512, 1) void k_fused(const float2* __restrict__ act,
                                                  const float2* __restrict__ wts,
                                                  float2* __restrict__ out) {
  const int b = blockIdx.x, tid = threadIdx.x;
  const int wid = tid >> 5, lane = tid & 31;
  const bool prod = (wid < 8);
  const int o = wid - 8;                     // consumer warp's output tau
  float2* Fs = smem_;                        // 288 complex activations
  float2* buf0 = smem_ + 288;                // mid buffer A
  float2* buf1 = buf0 + BUFSTR;              // mid buffer B

  for (int i = tid; i < 288; i += 512) Fs[i] = act[b * 288 + i];
  float2 acc[36];
  if (!prod) {
#pragma unroll
    for (int i = 0; i < 36; i++) { acc[i].x = 0.f; acc[i].y = 0.f; }
  }
  __syncthreads();

  // producers fill buf(r+1) while consumers drain buf(r)
  if (prod) roundA<3, 3, 5, 4, 2, 1, 5, 0>(Fs, buf0, wid, lane);
  __syncthreads();
  if (prod) roundA<4, 4, 4, 3, 5, 1, 3, 0>(Fs, buf1, wid, lane);
  else      roundB<3, 3, 5, 4, 2, 1, 5, 0>(buf0, wts, acc, o, lane);
  __syncthreads();
  if (prod) roundA<5, 5, 5, 3, 2, 2, 2, 0>(Fs, buf0, wid, lane);
  else      roundB<4, 4, 4, 3, 5, 1, 3, 0>(buf1, wts, acc, o, lane);
  __syncthreads();
  if (prod) roundA<3, 2, 4, 2, 3, 1, 1, 1>(Fs, buf1, wid, lane);
  else      roundB<5, 5, 5, 3, 2, 2, 2, 0>(buf0, wts, acc, o, lane);
  __syncthreads();
  if (prod) roundA<4, 1, 5, 2, 4, 0, 1, 0>(Fs, buf0, wid, lane);
  else      roundB<3, 2, 4, 2, 3, 1, 1, 1>(buf1, wts, acc, o, lane);
  __syncthreads();
  if (prod) {  // final pair (0,0): warps 0-1 cover its 64 channels
    const int p = wid >> 1, ch = ((wid & 1) << 5) | lane;
    if (p == 0) pairA_all<0, 0, 0>(Fs, buf1, ch);
  } else {
    roundB<4, 1, 5, 2, 4, 0, 1, 0>(buf0, wts, acc, o, lane);
  }
  __syncthreads();
  if (!prod) {
    pairB_o<0, 0>(buf1, wts, acc, o, lane);

    // epilogue: shfl-reduce lane partials for all 36 rows, lane 0 stores
#pragma unroll
    for (int L = 0; L < 6; L++) {
#pragma unroll
      for (int m = 0; m < 2 * L + 1; m++) {
        float2 v = acc[L * L + m];
#pragma unroll
        for (int off = 16; off; off >>= 1) {
          v.x += __shfl_xor_sync(0xffffffffu, v.x, off);
          v.y += __shfl_xor_sync(0xffffffffu, v.y, off);
        }
        if (lane == 0) out[b * 288 + ACTOFF_f(L) + o * (2 * L + 1) + m] = v;
      }
    }
  }
}

// ===================== launch =====================
extern "C" void kernel_launch(void* const* d_in, const int* in_sizes, int n_in,
                              void* d_out, int out_size) {
  const float2* act = nullptr;
  const float2* wts = nullptr;
  const float* mstd = nullptr;
  int B = 1024;
  for (int i = 0; i < n_in; i++) {
    if (in_sizes[i] == 4416) mstd = (const float*)d_in[i];
    else if (in_sizes[i] == 70656) wts = (const float2*)d_in[i];
    else { act = (const float2*)d_in[i]; B = in_sizes[i] / 576; }
  }
  float2* out = (float2*)d_out;

  k_invstd<<<(4416 + 255) / 256, 256>>>(mstd);

  const int smem = (288 + 2 * BUFSTR) * (int)sizeof(float2);  // ~104.7 KB
  cudaFuncSetAttribute(k_fused, cudaFuncAttributeMaxDynamicSharedMemorySize, smem);
  k_fused<<<B, 512, smem>>>(act, wts, out);
}

// round 15
// speedup vs baseline: 1.3956x; 1.0678x over previous
#include <cuda_runtime.h>

// ===================== compile-time CG machinery (host+device constexpr) =====================
__host__ __device__ constexpr double cfact(int n) { double r = 1.0; for (int i = 2; i <= n; i++) r *= (double)i; return r; }
__host__ __device__ constexpr double csqrt_(double x) { double g = x > 1.0 ? x : 1.0; for (int i = 0; i < 100; i++) g = 0.5 * (g + x / g); return g; }
__host__ __device__ constexpr double cg_d(int l1, int l2, int l, int m1, int m2) {
  const int m = m1 + m2;
  if (m < -l || m > l) return 0.0;
  double pre = csqrt_((2 * l + 1) * cfact(l + l1 - l2) * cfact(l - l1 + l2) * cfact(l1 + l2 - l) / cfact(l1 + l2 + l + 1));
  pre *= csqrt_(cfact(l + m) * cfact(l - m) * cfact(l1 - m1) * cfact(l1 + m1) * cfact(l2 - m2) * cfact(l2 + m2));
  double s = 0.0;
  for (int k = 0; k <= l1 + l2 - l; k++) {
    int e2 = l1 + l2 - l - k, e3 = l1 - m1 - k, e4 = l2 + m2 - k, e5 = l - l2 + m1 + k, e6 = l - l1 - m2 + k;
    if (e3 < 0 || e4 < 0 || e5 < 0 || e6 < 0) continue;
    double d = cfact(k) * cfact(e2) * cfact(e3) * cfact(e4) * cfact(e5) * cfact(e6);
    s += ((k & 1) ? -1.0 : 1.0) / d;
  }
  double v = pre * s;
  if (v < 1e-12 && v > -1e-12) return 0.0;
  return v;
}
__host__ __device__ constexpr int cmax_i(int a, int b) { return a > b ? a : b; }
__host__ __device__ constexpr int cmin_i(int a, int b) { return a < b ? a : b; }
__host__ __device__ constexpr int lmax_of(int a, int b) { return (a + b < 5) ? (a + b) : 5; }
__host__ __device__ constexpr int NTA_f(int l)     { return l == 0 ? 384 : l == 1 ? 640 : l == 2 ? 832 : l == 3 ? 896 : l == 4 ? 896 : 768; }
__host__ __device__ constexpr int STDOFF_f(int l)  { return l == 0 ? 0 : l == 1 ? 384 : l == 2 ? 1024 : l == 3 ? 1856 : l == 4 ? 2752 : 3648; }
__host__ __device__ constexpr int WOFF_f(int l)    { return l == 0 ? 0 : l == 1 ? 3072 : l == 2 ? 8192 : l == 3 ? 14848 : l == 4 ? 22016 : 29184; }
__host__ __device__ constexpr int ACTOFF_f(int l)  { return l == 0 ? 0 : l == 1 ? 8 : l == 2 ? 32 : l == 3 ? 72 : l == 4 ? 128 : 200; }
__host__ __device__ constexpr int chanoff_f(int L, int l1, int l2) {
  int off = 0;
  for (int a = 0; a <= 5; a++)
    for (int b = 0; b <= a; b++) {
      int lm = lmax_of(a, b);
      for (int l = a - b; l <= lm; l++)
        if (l == L) { if (a == l1 && b == l2) return off; off += 64; }
    }
  return 0;
}
__host__ __device__ constexpr int sumnl_f(int a, int b) { int s = 0; for (int l = a - b; l <= lmax_of(a, b); l++) s += 2 * l + 1; return s; }
__host__ __device__ constexpr int nls_f(int a, int b) { return lmax_of(a, b) - (a - b) + 1; }
// padded per-channel stride: sumnl + NLS (each section padded to even), rounded to ≡2 mod 4
__host__ __device__ constexpr int srowp_f(int a, int b) {
  int x = sumnl_f(a, b) + nls_f(a, b);
  while ((x & 3) != 2) x++;
  return x;
}
// even section starts in padded layout
__host__ __device__ constexpr int rowoff2_f(int l1, int l2, int li) { return li * (2 * (l1 - l2) + li + 1); }
// packed frag layout (registers)
__host__ __device__ constexpr int rowoff_f(int l1, int l2, int li) { return li * (2 * (l1 - l2) + li); }
// greedy chunking: each chunk <= 10 rows (keeps stage-A frag small)
__host__ __device__ constexpr int chunk_end_f(int l1, int l2, int lib) {
  int lmin = l1 - l2, nls = lmax_of(l1, l2) - lmin + 1;
  int rows = 0, lie = lib;
  for (int li = lib; li < nls; li++) {
    int L = lmin + li;
    if (rows + 2 * L + 1 > 10 && li > lib) break;
    rows += 2 * L + 1; lie = li;
  }
  return lie;
}

template <int L1, int L2>
struct PairCG {
  static constexpr int LMIN = L1 - L2, LMAX = lmax_of(L1, L2), NLS = LMAX - LMIN + 1;
  static constexpr int NL1 = 2 * L1 + 1, NL2 = 2 * L2 + 1;
  float v[NLS][NL1][NL2];
  int stdidx[NLS];
  int widx[NLS];
  int ntl[NLS];
  __host__ __device__ constexpr PairCG() : v(), stdidx(), widx(), ntl() {
    for (int li = 0; li < NLS; li++) {
      const int L = LMIN + li;
      for (int a = 0; a < NL1; a++)
        for (int c = 0; c < NL2; c++)
          v[li][a][c] = (float)cg_d(L1, L2, L, a - L1, c - L2);
      stdidx[li] = STDOFF_f(L) + chanoff_f(L, L1, L2);
      widx[li]   = WOFF_f(L) + chanoff_f(L, L1, L2);
      ntl[li]    = NTA_f(L);
    }
  }
};

// ===================== device globals =====================
__device__ float d_invstd[4416];

__global__ void k_invstd(const float* __restrict__ s) {
  int i = blockIdx.x * blockDim.x + threadIdx.x;
  if (i < 4416) d_invstd[i] = 1.0f / (s[i] + 1e-5f);
}

#define BUFSTR 7680  // complex units per blk buffer (max round srowp sum = 120)

// ===================== stage A chunk: thread = channel, li in [LIB,LIE] =====================
template <int L1, int L2, int LIB, int LIE>
__device__ __forceinline__ void pairA_chunk(const float2* __restrict__ Fs, float2* __restrict__ blk, int ch) {
  constexpr PairCG<L1, L2> CG{};
  constexpr int NL1 = 2 * L1 + 1, NL2 = 2 * L2 + 1, LMIN = L1 - L2;
  constexpr int SROWP = srowp_f(L1, L2);
  constexpr int CB = rowoff_f(L1, L2, LIB);
  constexpr int CROWS = rowoff_f(L1, L2, LIE + 1) - CB;
  const int t = ch >> 3, s = ch & 7;
  const float2* Ap = Fs + ACTOFF_f(L1) + t * NL1;
  const float2* Bp = Fs + ACTOFF_f(L2) + s * NL2;
  float2 a[NL1];
#pragma unroll
  for (int i = 0; i < NL1; i++) a[i] = Ap[i];
  float2 frag[CROWS];
#pragma unroll
  for (int i = 0; i < CROWS; i++) { frag[i].x = 0.f; frag[i].y = 0.f; }
#pragma unroll
  for (int m2 = 0; m2 < NL2; m2++) {
    const float2 b = Bp[m2];
#pragma unroll
    for (int m1 = 0; m1 < NL1; m1++) {
      const float px = a[m1].x * b.x - a[m1].y * b.y;
      const float py = a[m1].x * b.y + a[m1].y * b.x;
#pragma unroll
      for (int li = LIB; li <= LIE; li++) {
        const int L = LMIN + li;
        const int midx = (m1 - L1) + (m2 - L2) + L;
        if (midx >= 0 && midx < 2 * L + 1) {
          const float c = CG.v[li][m1][m2];
          if (c != 0.f) {
            const int fi = rowoff_f(L1, L2, li) - CB + midx;
            frag[fi].x += c * px;
            frag[fi].y += c * py;
          }
        }
      }
    }
  }
  // write out: per li section (even-aligned start), float4 row pairs + float2 tail
#pragma unroll
  for (int li = LIB; li <= LIE; li++) {
    const int L = LMIN + li;
    const int nl = 2 * L + 1;
    const float istd = d_invstd[CG.stdidx[li] + ch];
    float2* sp = blk + ch * SROWP + rowoff2_f(L1, L2, li);
    const int fb = rowoff_f(L1, L2, li) - CB;
#pragma unroll
    for (int m = 0; m + 1 < nl; m += 2) {
      const float2 f0 = frag[fb + m], f1 = frag[fb + m + 1];
      *reinterpret_cast<float4*>(sp + m) =
          make_float4(f0.x * istd, f0.y * istd, f1.x * istd, f1.y * istd);
    }
    const float2 ft = frag[fb + nl - 1];
    sp[nl - 1] = make_float2(ft.x * istd, ft.y * istd);
  }
}

// chunks assigned round-robin to the two 64-thread halves (ah = 0/1) of a pair's thread group
template <int L1, int L2, int LIB, int IDX>
__device__ __forceinline__ void pairA_rec(const float2* __restrict__ Fs, float2* __restrict__ blk, int ch, int ah) {
  constexpr int LIE = chunk_end_f(L1, L2, LIB);
  if ((IDX & 1) == ah) pairA_chunk<L1, L2, LIB, LIE>(Fs, blk, ch);
  if constexpr (LIE < PairCG<L1, L2>::NLS - 1) pairA_rec<L1, L2, LIE + 1, IDX + 1>(Fs, blk, ch, ah);
}

// ===================== stage B: warp = (o, H); lane = channel; acc[18] rows ================
template <int L1, int L2, int H>
__device__ __forceinline__ void pairB_half(const float2* __restrict__ blk, const float2* __restrict__ wts,
                                           float2 (&acc)[18], int o, int lane) {
  constexpr PairCG<L1, L2> CG{};
  constexpr int NLS = PairCG<L1, L2>::NLS, LMIN = L1 - L2;
  constexpr int SROWP = srowp_f(L1, L2);
#pragma unroll
  for (int li = 0; li < NLS; li++) {
    const int L = LMIN + li;
    const int LO = L * L, nl = 2 * L + 1;
    const int mlo = cmax_i(0, 18 * H - LO);      // always even for this partition
    const int mhi = cmin_i(nl, 18 * H + 18 - LO);
    if (mlo < mhi) {
      const int ro2 = rowoff2_f(L1, L2, li);
      const float2* wp = wts + CG.widx[li] + o * CG.ntl[li];
#pragma unroll
      for (int h2 = 0; h2 < 2; h2++) {
        const int c = lane + 32 * h2;
        const float2 w = __ldg(wp + c);
        const float2* mp = blk + c * SROWP + ro2;
#pragma unroll
        for (int m = mlo; m + 1 < mhi; m += 2) {
          const float4 v = *reinterpret_cast<const float4*>(mp + m);
          acc[LO + m - 18 * H].x += w.x * v.x - w.y * v.y;
          acc[LO + m - 18 * H].y += w.x * v.y + w.y * v.x;
          acc[LO + m + 1 - 18 * H].x += w.x * v.z - w.y * v.w;
          acc[LO + m + 1 - 18 * H].y += w.x * v.w + w.y * v.z;
        }
        if (((mhi - mlo) & 1) != 0) {
          const float2 mv = mp[mhi - 1];
          acc[LO + mhi - 1 - 18 * H].x += w.x * mv.x - w.y * mv.y;
          acc[LO + mhi - 1 - 18 * H].y += w.x * mv.y + w.y * mv.x;
        }
      }
    }
  }
}

// ===================== round pieces =====================
template <int A0, int B0, int A1, int B1, int A2, int B2, int A3, int B3>
__device__ __forceinline__ void roundA(const float2* __restrict__ Fs, float2* __restrict__ blk, int tid) {
  const int p = tid >> 7, t = tid & 127, ch = t & 63, ah = t >> 6;
  constexpr int T0 = 0;
  constexpr int T1 = T0 + 64 * srowp_f(A0, B0);
  constexpr int T2 = T1 + 64 * srowp_f(A1, B1);
  constexpr int T3 = T2 + 64 * srowp_f(A2, B2);
  if (p == 0)      pairA_rec<A0, B0, 0, 0>(Fs, blk + T0, ch, ah);
  else if (p == 1) pairA_rec<A1, B1, 0, 0>(Fs, blk + T1, ch, ah);
  else if (p == 2) pairA_rec<A2, B2, 0, 0>(Fs, blk + T2, ch, ah);
  else             pairA_rec<A3, B3, 0, 0>(Fs, blk + T3, ch, ah);
}

template <int A0, int B0, int A1, int B1, int A2, int B2, int A3, int B3>
__device__ __forceinline__ void roundB(const float2* __restrict__ blk, const float2* __restrict__ wts,
                                       float2 (&acc)[18], int o, int lane, int h) {
  constexpr int T0 = 0;
  constexpr int T1 = T0 + 64 * srowp_f(A0, B0);
  constexpr int T2 = T1 + 64 * srowp_f(A1, B1);
  constexpr int T3 = T2 + 64 * srowp_f(A2, B2);
  if (h == 0) {
    pairB_half<A0, B0, 0>(blk + T0, wts, acc, o, lane);
    pairB_half<A1, B1, 0>(blk + T1, wts, acc, o, lane);
    pairB_half<A2, B2, 0>(blk + T2, wts, acc, o, lane);
    pairB_half<A3, B3, 0>(blk + T3, wts, acc, o, lane);
  } else {
    pairB_half<A0, B0, 1>(blk + T0, wts, acc, o, lane);
    pairB_half<A1, B1, 1>(blk + T1, wts, acc, o, lane);
    pairB_half<A2, B2, 1>(blk + T2, wts, acc, o, lane);
    pairB_half<A3, B3, 1>(blk + T3, wts, acc, o, lane);
  }
}

// ===================== fused kernel: software-pipelined rounds, double-buffered mid =========
extern __shared__ float2 smem_[];

__global__ __launch_bounds__(512, 1) void k_fused(const float2* __restrict__ act,
                                                  const float2* __restrict__ wts,
                                                  float2* __restrict__ out) {
  const int b = blockIdx.x, tid = threadIdx.x;
  const int warp = tid >> 5, lane = tid & 31;
  const int o = warp & 7, h = warp >> 3;   // warp owns output tau o, row-half h
  float2* Fs = smem_;                       // 288 complex activations
  float2* buf0 = smem_ + 288;               // mid buffer A
  float2* buf1 = buf0 + BUFSTR;             // mid buffer B

  for (int i = tid; i < 288; i += 512) Fs[i] = act[b * 288 + i];
  float2 acc[18];
#pragma unroll
  for (int i = 0; i < 18; i++) { acc[i].x = 0.f; acc[i].y = 0.f; }
  __syncthreads();

  // pipeline: A(r+1) overlaps B(r)
  roundA<3, 3, 5, 4, 2, 1, 5, 0>(Fs, buf0, tid);
  __syncthreads();
  roundA<4, 4, 4, 3, 5, 1, 3, 0>(Fs, buf1, tid);
  roundB<3, 3, 5, 4, 2, 1, 5, 0>(buf0, wts, acc, o, lane, h);
  __syncthreads();
  roundA<5, 5, 5, 3, 2, 2, 2, 0>(Fs, buf0, tid);
  roundB<4, 4, 4, 3, 5, 1, 3, 0>(buf1, wts, acc, o, lane, h);
  __syncthreads();
  roundA<3, 2, 4, 2, 3, 1, 1, 1>(Fs, buf1, tid);
  roundB<5, 5, 5, 3, 2, 2, 2, 0>(buf0, wts, acc, o, lane, h);
  __syncthreads();
  roundA<4, 1, 5, 2, 4, 0, 1, 0>(Fs, buf0, tid);
  roundB<3, 2, 4, 2, 3, 1, 1, 1>(buf1, wts, acc, o, lane, h);
  __syncthreads();
  {  // A of final pair (0,0) into buf1 (group 0 only), overlapped with B(r4)
    const int p = tid >> 7, t = tid & 127, ch = t & 63, ah = t >> 6;
    if (p == 0) pairA_rec<0, 0, 0, 0>(Fs, buf1, ch, ah);
  }
  roundB<4, 1, 5, 2, 4, 0, 1, 0>(buf0, wts, acc, o, lane, h);
  __syncthreads();
  if (h == 0) pairB_half<0, 0, 0>(buf1, wts, acc, o, lane);

  // epilogue: shfl-reduce lane partials for the warp's 18 rows, lane 0 stores
#pragma unroll
  for (int i = 0; i < 18; i++) {
    float2 v = acc[i];
#pragma unroll
    for (int off = 16; off; off >>= 1) {
      v.x += __shfl_xor_sync(0xffffffffu, v.x, off);
      v.y += __shfl_xor_sync(0xffffffffu, v.y, off);
    }
    if (lane == 0) {
      const int r = 18 * h + i;
      const int l = (r >= 25) ? 5 : (r >= 16) ? 4 : (r >= 9) ? 3 : (r >= 4) ? 2 : (r >= 1) ? 1 : 0;
      const int m = r - l * l;
      out[b * 288 + ACTOFF_f(l) + o * (2 * l + 1) + m] = v;
    }
  }
}

// ===================== launch =====================
extern "C" void kernel_launch(void* const* d_in, const int* in_sizes, int n_in,
                              void* d_out, int out_size) {
  const float2* act = nullptr;
  const float2* wts = nullptr;
  const float* mstd = nullptr;
  int B = 1024;
  for (int i = 0; i < n_in; i++) {
    if (in_sizes[i] == 4416) mstd = (const float*)d_in[i];
    else if (in_sizes[i] == 70656) wts = (const float2*)d_in[i];
    else { act = (const float2*)d_in[i]; B = in_sizes[i] / 576; }
  }
  float2* out = (float2*)d_out;

  k_invstd<<<(4416 + 255) / 256, 256>>>(mstd);

  const int smem = (288 + 2 * BUFSTR) * (int)sizeof(float2);  // ~122.2 KB
  cudaFuncSetAttribute(k_fused, cudaFuncAttributeMaxDynamicSharedMemorySize, smem);
  k_fused<<<B, 512, smem>>>(act, wts, out);
}

// round 16
// speedup vs baseline: 1.4034x; 1.0056x over previous
#include <cuda_runtime.h>

// ===================== compile-time CG machinery (host+device constexpr) =====================
__host__ __device__ constexpr double cfact(int n) { double r = 1.0; for (int i = 2; i <= n; i++) r *= (double)i; return r; }
__host__ __device__ constexpr double csqrt_(double x) { double g = x > 1.0 ? x : 1.0; for (int i = 0; i < 100; i++) g = 0.5 * (g + x / g); return g; }
__host__ __device__ constexpr double cg_d(int l1, int l2, int l, int m1, int m2) {
  const int m = m1 + m2;
  if (m < -l || m > l) return 0.0;
  double pre = csqrt_((2 * l + 1) * cfact(l + l1 - l2) * cfact(l - l1 + l2) * cfact(l1 + l2 - l) / cfact(l1 + l2 + l + 1));
  pre *= csqrt_(cfact(l + m) * cfact(l - m) * cfact(l1 - m1) * cfact(l1 + m1) * cfact(l2 - m2) * cfact(l2 + m2));
  double s = 0.0;
  for (int k = 0; k <= l1 + l2 - l; k++) {
    int e2 = l1 + l2 - l - k, e3 = l1 - m1 - k, e4 = l2 + m2 - k, e5 = l - l2 + m1 + k, e6 = l - l1 - m2 + k;
    if (e3 < 0 || e4 < 0 || e5 < 0 || e6 < 0) continue;
    double d = cfact(k) * cfact(e2) * cfact(e3) * cfact(e4) * cfact(e5) * cfact(e6);
    s += ((k & 1) ? -1.0 : 1.0) / d;
  }
  double v = pre * s;
  if (v < 1e-12 && v > -1e-12) return 0.0;
  return v;
}
__host__ __device__ constexpr int cmax_i(int a, int b) { return a > b ? a : b; }
__host__ __device__ constexpr int cmin_i(int a, int b) { return a < b ? a : b; }
__host__ __device__ constexpr int lmax_of(int a, int b) { return (a + b < 5) ? (a + b) : 5; }
__host__ __device__ constexpr int NTA_f(int l)     { return l == 0 ? 384 : l == 1 ? 640 : l == 2 ? 832 : l == 3 ? 896 : l == 4 ? 896 : 768; }
__host__ __device__ constexpr int STDOFF_f(int l)  { return l == 0 ? 0 : l == 1 ? 384 : l == 2 ? 1024 : l == 3 ? 1856 : l == 4 ? 2752 : 3648; }
__host__ __device__ constexpr int WOFF_f(int l)    { return l == 0 ? 0 : l == 1 ? 3072 : l == 2 ? 8192 : l == 3 ? 14848 : l == 4 ? 22016 : 29184; }
__host__ __device__ constexpr int ACTOFF_f(int l)  { return l == 0 ? 0 : l == 1 ? 8 : l == 2 ? 32 : l == 3 ? 72 : l == 4 ? 128 : 200; }
__host__ __device__ constexpr int chanoff_f(int L, int l1, int l2) {
  int off = 0;
  for (int a = 0; a <= 5; a++)
    for (int b = 0; b <= a; b++) {
      int lm = lmax_of(a, b);
      for (int l = a - b; l <= lm; l++)
        if (l == L) { if (a == l1 && b == l2) return off; off += 64; }
    }
  return 0;
}
__host__ __device__ constexpr int sumnl_f(int a, int b) { int s = 0; for (int l = a - b; l <= lmax_of(a, b); l++) s += 2 * l + 1; return s; }
__host__ __device__ constexpr int nls_f(int a, int b) { return lmax_of(a, b) - (a - b) + 1; }
// padded per-channel stride: sumnl + NLS (each section padded to even), rounded to ≡2 mod 4
__host__ __device__ constexpr int srowp_f(int a, int b) {
  int x = sumnl_f(a, b) + nls_f(a, b);
  while ((x & 3) != 2) x++;
  return x;
}
// even section starts in padded layout
__host__ __device__ constexpr int rowoff2_f(int l1, int l2, int li) { return li * (2 * (l1 - l2) + li + 1); }
// packed frag layout (registers)
__host__ __device__ constexpr int rowoff_f(int l1, int l2, int li) { return li * (2 * (l1 - l2) + li); }
// greedy chunking: each chunk <= 10 rows (keeps stage-A frag small)
__host__ __device__ constexpr int chunk_end_f(int l1, int l2, int lib) {
  int lmin = l1 - l2, nls = lmax_of(l1, l2) - lmin + 1;
  int rows = 0, lie = lib;
  for (int li = lib; li < nls; li++) {
    int L = lmin + li;
    if (rows + 2 * L + 1 > 10 && li > lib) break;
    rows += 2 * L + 1; lie = li;
  }
  return lie;
}

template <int L1, int L2>
struct PairCG {
  static constexpr int LMIN = L1 - L2, LMAX = lmax_of(L1, L2), NLS = LMAX - LMIN + 1;
  static constexpr int NL1 = 2 * L1 + 1, NL2 = 2 * L2 + 1;
  float v[NLS][NL1][NL2];
  int stdidx[NLS];
  int widx[NLS];
  int ntl[NLS];
  __host__ __device__ constexpr PairCG() : v(), stdidx(), widx(), ntl() {
    for (int li = 0; li < NLS; li++) {
      const int L = LMIN + li;
      for (int a = 0; a < NL1; a++)
        for (int c = 0; c < NL2; c++)
          v[li][a][c] = (float)cg_d(L1, L2, L, a - L1, c - L2);
      stdidx[li] = STDOFF_f(L) + chanoff_f(L, L1, L2);
      widx[li]   = WOFF_f(L) + chanoff_f(L, L1, L2);
      ntl[li]    = NTA_f(L);
    }
  }
};

// ===================== device globals =====================
__device__ float d_invstd[4416];

__global__ void k_invstd(const float* __restrict__ s) {
  int i = blockIdx.x * blockDim.x + threadIdx.x;
  if (i < 4416) d_invstd[i] = 1.0f / (s[i] + 1e-5f);
}

#define BUFSTR 10496  // complex units per blk buffer (max round srowp sum = 164)

// ===================== stage A chunk: thread = channel, li in [LIB,LIE] =====================
template <int L1, int L2, int LIB, int LIE>
__device__ __forceinline__ void pairA_chunk(const float2* __restrict__ Fs, float2* __restrict__ blk, int ch) {
  constexpr PairCG<L1, L2> CG{};
  constexpr int NL1 = 2 * L1 + 1, NL2 = 2 * L2 + 1, LMIN = L1 - L2;
  constexpr int SROWP = srowp_f(L1, L2);
  constexpr int CB = rowoff_f(L1, L2, LIB);
  constexpr int CROWS = rowoff_f(L1, L2, LIE + 1) - CB;
  const int t = ch >> 3, s = ch & 7;
  const float2* Ap = Fs + ACTOFF_f(L1) + t * NL1;
  const float2* Bp = Fs + ACTOFF_f(L2) + s * NL2;
  float2 a[NL1];
#pragma unroll
  for (int i = 0; i < NL1; i++) a[i] = Ap[i];
  float2 frag[CROWS];
#pragma unroll
  for (int i = 0; i < CROWS; i++) { frag[i].x = 0.f; frag[i].y = 0.f; }
#pragma unroll
  for (int m2 = 0; m2 < NL2; m2++) {
    const float2 b = Bp[m2];
#pragma unroll
    for (int m1 = 0; m1 < NL1; m1++) {
      const float px = a[m1].x * b.x - a[m1].y * b.y;
      const float py = a[m1].x * b.y + a[m1].y * b.x;
#pragma unroll
      for (int li = LIB; li <= LIE; li++) {
        const int L = LMIN + li;
        const int midx = (m1 - L1) + (m2 - L2) + L;
        if (midx >= 0 && midx < 2 * L + 1) {
          const float c = CG.v[li][m1][m2];
          if (c != 0.f) {
            const int fi = rowoff_f(L1, L2, li) - CB + midx;
            frag[fi].x += c * px;
            frag[fi].y += c * py;
          }
        }
      }
    }
  }
  // write out: per li section (even-aligned start), float4 row pairs + float2 tail
#pragma unroll
  for (int li = LIB; li <= LIE; li++) {
    const int L = LMIN + li;
    const int nl = 2 * L + 1;
    const float istd = d_invstd[CG.stdidx[li] + ch];
    float2* sp = blk + ch * SROWP + rowoff2_f(L1, L2, li);
    const int fb = rowoff_f(L1, L2, li) - CB;
#pragma unroll
    for (int m = 0; m + 1 < nl; m += 2) {
      const float2 f0 = frag[fb + m], f1 = frag[fb + m + 1];
      *reinterpret_cast<float4*>(sp + m) =
          make_float4(f0.x * istd, f0.y * istd, f1.x * istd, f1.y * istd);
    }
    const float2 ft = frag[fb + nl - 1];
    sp[nl - 1] = make_float2(ft.x * istd, ft.y * istd);
  }
}

// chunks assigned round-robin to the two 64-thread halves (ah = 0/1) of a pair's thread group
template <int L1, int L2, int LIB, int IDX>
__device__ __forceinline__ void pairA_rec(const float2* __restrict__ Fs, float2* __restrict__ blk, int ch, int ah) {
  constexpr int LIE = chunk_end_f(L1, L2, LIB);
  if ((IDX & 1) == ah) pairA_chunk<L1, L2, LIB, LIE>(Fs, blk, ch);
  if constexpr (LIE < PairCG<L1, L2>::NLS - 1) pairA_rec<L1, L2, LIE + 1, IDX + 1>(Fs, blk, ch, ah);
}

// ===================== stage B: warp = (o, H); lane = channel; acc[18] rows ================
template <int L1, int L2, int H>
__device__ __forceinline__ void pairB_half(const float2* __restrict__ blk, const float2* __restrict__ wts,
                                           float2 (&acc)[18], int o, int lane) {
  constexpr PairCG<L1, L2> CG{};
  constexpr int NLS = PairCG<L1, L2>::NLS, LMIN = L1 - L2;
  constexpr int SROWP = srowp_f(L1, L2);
#pragma unroll
  for (int li = 0; li < NLS; li++) {
    const int L = LMIN + li;
    const int LO = L * L, nl = 2 * L + 1;
    const int mlo = cmax_i(0, 18 * H - LO);      // always even for this partition
    const int mhi = cmin_i(nl, 18 * H + 18 - LO);
    if (mlo < mhi) {
      const int ro2 = rowoff2_f(L1, L2, li);
      const float2* wp = wts + CG.widx[li] + o * CG.ntl[li];
#pragma unroll
      for (int h2 = 0; h2 < 2; h2++) {
        const int c = lane + 32 * h2;
        const float2 w = __ldg(wp + c);
        const float2* mp = blk + c * SROWP + ro2;
#pragma unroll
        for (int m = mlo; m + 1 < mhi; m += 2) {
          const float4 v = *reinterpret_cast<const float4*>(mp + m);
          acc[LO + m - 18 * H].x += w.x * v.x - w.y * v.y;
          acc[LO + m - 18 * H].y += w.x * v.y + w.y * v.x;
          acc[LO + m + 1 - 18 * H].x += w.x * v.z - w.y * v.w;
          acc[LO + m + 1 - 18 * H].y += w.x * v.w + w.y * v.z;
        }
        if (((mhi - mlo) & 1) != 0) {
          const float2 mv = mp[mhi - 1];
          acc[LO + mhi - 1 - 18 * H].x += w.x * mv.x - w.y * mv.y;
          acc[LO + mhi - 1 - 18 * H].y += w.x * mv.y + w.y * mv.x;
        }
      }
    }
  }
}

// ===================== round pieces =====================
template <int A0, int B0, int A1, int B1, int A2, int B2, int A3, int B3>
__device__ __forceinline__ void roundA(const float2* __restrict__ Fs, float2* __restrict__ blk, int tid) {
  const int p = tid >> 7, t = tid & 127, ch = t & 63, ah = t >> 6;
  constexpr int T0 = 0;
  constexpr int T1 = T0 + 64 * srowp_f(A0, B0);
  constexpr int T2 = T1 + 64 * srowp_f(A1, B1);
  constexpr int T3 = T2 + 64 * srowp_f(A2, B2);
  if (p == 0)      pairA_rec<A0, B0, 0, 0>(Fs, blk + T0, ch, ah);
  else if (p == 1) pairA_rec<A1, B1, 0, 0>(Fs, blk + T1, ch, ah);
  else if (p == 2) pairA_rec<A2, B2, 0, 0>(Fs, blk + T2, ch, ah);
  else             pairA_rec<A3, B3, 0, 0>(Fs, blk + T3, ch, ah);
}

template <int A0, int B0, int A1, int B1, int A2, int B2, int A3, int B3>
__device__ __forceinline__ void roundB(const float2* __restrict__ blk, const float2* __restrict__ wts,
                                       float2 (&acc)[18], int o, int lane, int h) {
  constexpr int T0 = 0;
  constexpr int T1 = T0 + 64 * srowp_f(A0, B0);
  constexpr int T2 = T1 + 64 * srowp_f(A1, B1);
  constexpr int T3 = T2 + 64 * srowp_f(A2, B2);
  if (h == 0) {
    pairB_half<A0, B0, 0>(blk + T0, wts, acc, o, lane);
    pairB_half<A1, B1, 0>(blk + T1, wts, acc, o, lane);
    pairB_half<A2, B2, 0>(blk + T2, wts, acc, o, lane);
    pairB_half<A3, B3, 0>(blk + T3, wts, acc, o, lane);
  } else {
    pairB_half<A0, B0, 1>(blk + T0, wts, acc, o, lane);
    pairB_half<A1, B1, 1>(blk + T1, wts, acc, o, lane);
    pairB_half<A2, B2, 1>(blk + T2, wts, acc, o, lane);
    pairB_half<A3, B3, 1>(blk + T3, wts, acc, o, lane);
  }
}

// ===================== fused kernel: cost-balanced rounds, pipelined double buffer ==========
extern __shared__ float2 smem_[];

__global__ __launch_bounds__(512, 1) void k_fused(const float2* __restrict__ act,
                                                  const float2* __restrict__ wts,
                                                  float2* __restrict__ out) {
  const int b = blockIdx.x, tid = threadIdx.x;
  const int warp = tid >> 5, lane = tid & 31;
  const int o = warp & 7, h = warp >> 3;   // warp owns output tau o, row-half h
  float2* Fs = smem_;                       // 288 complex activations
  float2* buf0 = smem_ + 288;               // mid buffer A
  float2* buf1 = buf0 + BUFSTR;             // mid buffer B

  for (int i = tid; i < 288; i += 512) Fs[i] = act[b * 288 + i];
  float2 acc[18];
#pragma unroll
  for (int i = 0; i < 18; i++) { acc[i].x = 0.f; acc[i].y = 0.f; }
  __syncthreads();

  // rounds grouped by stage-A cost (descending): spans 726/315/165/63/9 vs old 495/486/726/180/165
  roundA<5, 5, 5, 4, 4, 4, 5, 3>(Fs, buf0, tid);
  __syncthreads();
  roundA<4, 3, 3, 3, 4, 2, 3, 2>(Fs, buf1, tid);
  roundB<5, 5, 5, 4, 4, 4, 5, 3>(buf0, wts, acc, o, lane, h);
  __syncthreads();
  roundA<5, 2, 2, 2, 4, 1, 5, 1>(Fs, buf0, tid);
  roundB<4, 3, 3, 3, 4, 2, 3, 2>(buf1, wts, acc, o, lane, h);
  __syncthreads();
  roundA<3, 1, 2, 1, 1, 1, 5, 0>(Fs, buf1, tid);
  roundB<5, 2, 2, 2, 4, 1, 5, 1>(buf0, wts, acc, o, lane, h);
  __syncthreads();
  roundA<4, 0, 3, 0, 2, 0, 1, 0>(Fs, buf0, tid);
  roundB<3, 1, 2, 1, 1, 1, 5, 0>(buf1, wts, acc, o, lane, h);
  __syncthreads();
  {  // A of final pair (0,0) into buf1 (group 0 only), overlapped with B(r4)
    const int p = tid >> 7, t = tid & 127, ch = t & 63, ah = t >> 6;
    if (p == 0) pairA_rec<0, 0, 0, 0>(Fs, buf1, ch, ah);
  }
  roundB<4, 0, 3, 0, 2, 0, 1, 0>(buf0, wts, acc, o, lane, h);
  __syncthreads();
  if (h == 0) pairB_half<0, 0, 0>(buf1, wts, acc, o, lane);

  // epilogue: shfl-reduce lane partials for the warp's 18 rows, lane 0 stores
#pragma unroll
  for (int i = 0; i < 18; i++) {
    float2 v = acc[i];
#pragma unroll
    for (int off = 16; off; off >>= 1) {
      v.x += __shfl_xor_sync(0xffffffffu, v.x, off);
      v.y += __shfl_xor_sync(0xffffffffu, v.y, off);
    }
    if (lane == 0) {
      const int r = 18 * h + i;
      const int l = (r >= 25) ? 5 : (r >= 16) ? 4 : (r >= 9) ? 3 : (r >= 4) ? 2 : (r >= 1) ? 1 : 0;
      const int m = r - l * l;
      out[b * 288 + ACTOFF_f(l) + o * (2 * l + 1) + m] = v;
    }
  }
}

// ===================== launch =====================
extern "C" void kernel_launch(void* const* d_in, const int* in_sizes, int n_in,
                              void* d_out, int out_size) {
  const float2* act = nullptr;
  const float2* wts = nullptr;
  const float* mstd = nullptr;
  int B = 1024;
  for (int i = 0; i < n_in; i++) {
    if (in_sizes[i] == 4416) mstd = (const float*)d_in[i];
    else if (in_sizes[i] == 70656) wts = (const float2*)d_in[i];
    else { act = (const float2*)d_in[i]; B = in_sizes[i] / 576; }
  }
  float2* out = (float2*)d_out;

  k_invstd<<<(4416 + 255) / 256, 256>>>(mstd);

  const int smem = (288 + 2 * BUFSTR) * (int)sizeof(float2);  // ~166.3 KB
  cudaFuncSetAttribute(k_fused, cudaFuncAttributeMaxDynamicSharedMemorySize, smem);
  k_fused<<<B, 512, smem>>>(act, wts, out);
}